// round 1
// baseline (speedup 1.0000x reference)
#include <cuda_runtime.h>

#define NB   8
#define ND   1024
#define DD   100
#define NV   30000
#define NC   512

#define TILE_V 128
#define TILE_D 64
#define NV_TILES ((NV + TILE_V - 1) / TILE_V)   // 235
#define ND_CHUNKS (ND / TILE_D)                 // 16

// Scratch (no allocations allowed): gathered+transposed A, per-(b,v) weighted sums, bin weights
__device__ float g_At[DD * NB * ND];      // [k][row], row = b*ND + d
__device__ float g_weighted[NB * NV];
__device__ float g_binw[16];

// ---------- small helpers ----------
__device__ __forceinline__ unsigned long long pack2(float a) {
    unsigned long long p;
    asm("mov.b64 %0, {%1, %1};" : "=l"(p) : "f"(a));
    return p;
}
__device__ __forceinline__ void unpack2(unsigned long long v, float& lo, float& hi) {
    asm("mov.b64 {%0, %1}, %2;" : "=f"(lo), "=f"(hi) : "l"(v));
}
__device__ __forceinline__ unsigned long long ffma2(unsigned long long a, unsigned long long b,
                                                    unsigned long long c) {
    unsigned long long d;
    asm("fma.rn.f32x2 %0, %1, %2, %3;" : "=l"(d) : "l"(a), "l"(b), "l"(c));
    return d;
}

// digitize against bin_mid = linspace(-0.5, 0.99, 15): uniform spacing -> closed form
__device__ __forceinline__ int digitize16(float s) {
    const float INV_STEP = 14.0f / 1.49f;
    int di = __float2int_rd((s + 0.5f) * INV_STEP) + 1;
    di = di < 0 ? 0 : di;
    di = di > 15 ? 15 : di;
    return di;
}

// ---------- kernel 0: bin weights ----------
__global__ void k_binw(const float* __restrict__ diff, const float* __restrict__ start) {
    if (threadIdx.x == 0) {
        float acc = start[0];
        for (int j = 0; j < 16; j++) {
            float d = diff[j];
            acc += d > 0.f ? d : 0.f;
            g_binw[j] = acc;
        }
    }
}

// ---------- kernel 1: gather emb rows into k-major scratch ----------
__global__ void k_gather(const int* __restrict__ doc_index, const float* __restrict__ emb) {
    int e = blockIdx.x * blockDim.x + threadIdx.x;
    const int total = DD * NB * ND;
    if (e < total) {
        int r = e % (NB * ND);
        int k = e / (NB * ND);
        g_At[e] = emb[doc_index[r] * DD + k];
    }
}

// ---------- kernel 2: fused GEMM + digitize + attn-weighted d-reduction ----------
// Shared layout (floats): Bs[100][128] @0, As[100][64] @12800, vpart[16][128] @19200, binw @21248
#define SMEM_FLOATS 21264

__global__ void __launch_bounds__(256, 2)
k_main(const float* __restrict__ Vv_T, const float* __restrict__ attn) {
    extern __shared__ float sm[];
    float* Bs      = sm;
    float* As      = sm + 12800;
    float* vpart   = sm + 19200;
    float* binw_sh = sm + 21248;

    const int tid = threadIdx.x;
    const int b   = blockIdx.y;
    const int v0  = blockIdx.x * TILE_V;
    const int td  = tid >> 4;   // 0..15 (d groups of 4)
    const int tv  = tid & 15;   // 0..15 (v groups of 8)

    if (tid < 16) binw_sh[tid] = g_binw[tid];

    // Load B tile [100 k][128 v] (pad out-of-range v with 0)
    for (int e = tid; e < DD * TILE_V; e += 256) {
        int k = e >> 7;
        int c = e & 127;
        int v = v0 + c;
        Bs[e] = (v < NV) ? Vv_T[k * NV + v] : 0.f;
    }
    __syncthreads();

    float vacc[8];
#pragma unroll
    for (int j = 0; j < 8; j++) vacc[j] = 0.f;

    const int rowbase = b * ND;

    for (int dc = 0; dc < ND_CHUNKS; ++dc) {
        const int d0 = dc * TILE_D;
        // Load A chunk [100 k][64 d] from k-major scratch (coalesced)
        for (int e = tid; e < DD * TILE_D; e += 256) {
            int k  = e >> 6;
            int dl = e & 63;
            As[e] = g_At[k * (NB * ND) + rowbase + d0 + dl];
        }
        __syncthreads();

        unsigned long long acc[16];
#pragma unroll
        for (int i = 0; i < 16; i++) acc[i] = 0ull;

        const float* Ab = As + td * 4;
        const float* Bb = Bs + tv * 8;

#pragma unroll 10
        for (int k = 0; k < DD; k++) {
            float4 a4 = *(const float4*)(Ab + k * 64);
            unsigned long long ap[4];
            ap[0] = pack2(a4.x);
            ap[1] = pack2(a4.y);
            ap[2] = pack2(a4.z);
            ap[3] = pack2(a4.w);
            const ulonglong2* bp = (const ulonglong2*)(Bb + k * 128);
            ulonglong2 q0 = bp[0];
            ulonglong2 q1 = bp[1];
            unsigned long long bq[4];
            bq[0] = q0.x; bq[1] = q0.y; bq[2] = q1.x; bq[3] = q1.y;
#pragma unroll
            for (int i = 0; i < 4; i++)
#pragma unroll
                for (int j = 0; j < 4; j++)
                    acc[i * 4 + j] = ffma2(ap[i], bq[j], acc[i * 4 + j]);
        }

        // epilogue: digitize -> bin weight -> attn-weighted accumulate over d
#pragma unroll
        for (int i = 0; i < 4; i++) {
            float attn_d = __ldg(&attn[rowbase + d0 + td * 4 + i]);
#pragma unroll
            for (int jp = 0; jp < 4; jp++) {
                float s0, s1;
                unpack2(acc[i * 4 + jp], s0, s1);
                vacc[2 * jp]     += attn_d * binw_sh[digitize16(s0)];
                vacc[2 * jp + 1] += attn_d * binw_sh[digitize16(s1)];
            }
        }
        __syncthreads();  // before next As overwrite
    }

    // cross-thread reduction over td (16 partials per v column)
#pragma unroll
    for (int j = 0; j < 8; j++) vpart[td * 128 + tv * 8 + j] = vacc[j];
    __syncthreads();
    if (tid < 128) {
        float s = 0.f;
#pragma unroll
        for (int t = 0; t < 16; t++) s += vpart[t * 128 + tid];
        int v = v0 + tid;
        if (v < NV) g_weighted[b * NV + v] = s;
    }
}

// ---------- kernel 3: fused phi L1-norm + final GEMM ----------
// One block per 4 concept rows; reads phi once, computes 8 dots + L1 per row.
__global__ void __launch_bounds__(256)
k_final(const float* __restrict__ phi, float* __restrict__ out) {
    const int n0  = blockIdx.x * 4;
    const int tid = threadIdx.x;

    float acc[4][8];
    float l1[4];
#pragma unroll
    for (int r = 0; r < 4; r++) {
        l1[r] = 0.f;
#pragma unroll
        for (int bb = 0; bb < 8; bb++) acc[r][bb] = 0.f;
    }

    for (int base = tid * 4; base < NV; base += 1024) {
        float4 w[8];
#pragma unroll
        for (int bb = 0; bb < 8; bb++)
            w[bb] = *(const float4*)&g_weighted[bb * NV + base];
#pragma unroll
        for (int r = 0; r < 4; r++) {
            float4 p = *(const float4*)&phi[(n0 + r) * NV + base];
            l1[r] += fabsf(p.x) + fabsf(p.y) + fabsf(p.z) + fabsf(p.w);
#pragma unroll
            for (int bb = 0; bb < 8; bb++) {
                acc[r][bb] += p.x * w[bb].x + p.y * w[bb].y + p.z * w[bb].z + p.w * w[bb].w;
            }
        }
    }

    // reduce 36 values across the block: warp shuffle then cross-warp via smem
    const unsigned mask = 0xffffffffu;
#pragma unroll
    for (int r = 0; r < 4; r++) {
#pragma unroll
        for (int bb = 0; bb < 8; bb++)
#pragma unroll
            for (int o = 16; o > 0; o >>= 1)
                acc[r][bb] += __shfl_down_sync(mask, acc[r][bb], o);
#pragma unroll
        for (int o = 16; o > 0; o >>= 1)
            l1[r] += __shfl_down_sync(mask, l1[r], o);
    }

    __shared__ float red[8][36];
    __shared__ float tot[36];
    const int wid = tid >> 5, lane = tid & 31;
    if (lane == 0) {
#pragma unroll
        for (int r = 0; r < 4; r++) {
#pragma unroll
            for (int bb = 0; bb < 8; bb++) red[wid][r * 9 + bb] = acc[r][bb];
            red[wid][r * 9 + 8] = l1[r];
        }
    }
    __syncthreads();
    if (tid < 36) {
        float s = 0.f;
#pragma unroll
        for (int w8 = 0; w8 < 8; w8++) s += red[w8][tid];
        tot[tid] = s;
    }
    __syncthreads();
    if (tid < 32) {
        int r  = tid >> 3;
        int bb = tid & 7;
        float l = tot[r * 9 + 8];
        out[bb * NC + (n0 + r)] = tot[r * 9 + bb] / fmaxf(l, 1e-12f);
    }
}

// ---------- launcher ----------
extern "C" void kernel_launch(void* const* d_in, const int* in_sizes, int n_in,
                              void* d_out, int out_size) {
    const int*   doc_index = (const int*)d_in[0];
    const float* attn      = (const float*)d_in[1];
    const float* emb       = (const float*)d_in[2];
    const float* vvt       = (const float*)d_in[3];
    const float* phi       = (const float*)d_in[4];
    const float* diff      = (const float*)d_in[5];
    const float* start     = (const float*)d_in[6];
    float* out = (float*)d_out;

    k_binw<<<1, 32>>>(diff, start);

    const int total = DD * NB * ND;
    k_gather<<<(total + 255) / 256, 256>>>(doc_index, emb);

    size_t smem = SMEM_FLOATS * sizeof(float);  // 85056 B
    cudaFuncSetAttribute(k_main, cudaFuncAttributeMaxDynamicSharedMemorySize, (int)smem);
    dim3 grid(NV_TILES, NB);
    k_main<<<grid, 256, smem>>>(vvt, attn);

    k_final<<<NC / 4, 256>>>(phi, out);
}

// round 2
// speedup vs baseline: 2.6061x; 2.6061x over previous
#include <cuda_runtime.h>
#include <cuda_bf16.h>
#include <cstdint>

#define NB   8
#define ND   1024
#define DD   100
#define NV   30000
#define NC   512

#define K3   320              // 3*100 padded to 320 (pad region zero in both operands)
#define NVP  30208            // 118 * 256
#define TILE_N 256
#define TILE_M 128
#define N_VT (NVP / TILE_N)   // 118
#define NDC  (ND / TILE_M)    // 8
#define KC   80               // K chunk held per A stage
#define NKC  (K3 / KC)        // 4

#define B_PITCH 656           // 41 * 16B (odd 16B units -> conflict-free ldmatrix)
#define A_PITCH 176           // 11 * 16B

#define BS_BYTES (TILE_N * B_PITCH)           // 167936
#define AS_BYTES (TILE_M * A_PITCH)           // 22528
#define SMEM_MAIN (BS_BYTES + 2*AS_BYTES + 128*4 + 512*4)  // 215552

#define INV_STEP (14.0f / 1.49f)

// -------- device scratch (no allocations allowed) --------
__device__ __nv_bfloat16 g_Acat[(size_t)NB * ND * K3];   // [row][k']  row = b*ND+d
__device__ __nv_bfloat16 g_Bcat[(size_t)NVP * K3];       // [v][k']
__device__ float g_weighted[NB * NVP];
__device__ float g_binw[16];

// -------- helpers --------
__device__ __forceinline__ uint32_t smem_u32(const void* p) {
    return (uint32_t)__cvta_generic_to_shared(p);
}
__device__ __forceinline__ void cpa16(uint32_t dst, const void* src) {
    asm volatile("cp.async.cg.shared.global [%0], [%1], 16;" :: "r"(dst), "l"(src));
}
__device__ __forceinline__ void cpa_commit() { asm volatile("cp.async.commit_group;"); }
__device__ __forceinline__ void cpa_wait0()  { asm volatile("cp.async.wait_group 0;"); }

__device__ __forceinline__ void ldm4(uint32_t& r0, uint32_t& r1, uint32_t& r2, uint32_t& r3,
                                     uint32_t addr) {
    asm volatile("ldmatrix.sync.aligned.m8n8.x4.shared.b16 {%0,%1,%2,%3}, [%4];"
                 : "=r"(r0), "=r"(r1), "=r"(r2), "=r"(r3) : "r"(addr));
}
__device__ __forceinline__ void mma16816(float* c, const uint32_t* a, const uint32_t* b) {
    asm volatile(
        "mma.sync.aligned.m16n8k16.row.col.f32.bf16.bf16.f32 "
        "{%0,%1,%2,%3}, {%4,%5,%6,%7}, {%8,%9}, {%0,%1,%2,%3};"
        : "+f"(c[0]), "+f"(c[1]), "+f"(c[2]), "+f"(c[3])
        : "r"(a[0]), "r"(a[1]), "r"(a[2]), "r"(a[3]), "r"(b[0]), "r"(b[1]));
}

// -------- kernel 0: bin weights --------
__global__ void k_binw(const float* __restrict__ diff, const float* __restrict__ start) {
    if (threadIdx.x == 0) {
        float acc = start[0];
        for (int j = 0; j < 16; j++) {
            float d = diff[j];
            acc += d > 0.f ? d : 0.f;
            g_binw[j] = acc;
        }
    }
}

// -------- kernel 1: gather + bf16 split of A rows:  A_cat = [hi | hi | lo], pad 0 --------
__global__ void k_splitA(const int* __restrict__ doc_index, const float* __restrict__ emb) {
    int e = blockIdx.x * blockDim.x + threadIdx.x;
    if (e >= NB * ND * K3) return;
    int r = e / K3;
    int k = e - r * K3;
    __nv_bfloat16 out = __float2bfloat16(0.f);
    if (k < 300) {
        int kk = k, region = 0;
        if (k >= 200)      { kk = k - 200; region = 2; }
        else if (k >= 100) { kk = k - 100; region = 1; }
        float val = emb[(size_t)doc_index[r] * DD + kk];
        __nv_bfloat16 hi = __float2bfloat16(val);
        if (region < 2) out = hi;
        else            out = __float2bfloat16(val - __bfloat162float(hi));
    }
    g_Acat[e] = out;
}

// -------- kernel 2: transpose + bf16 split of B:  B_cat = [hi | lo | hi], pad 0 --------
// block: 128 v-rows; smem staging pitch 330 bf16 (165 words, odd stride -> conflict-free)
__global__ void k_splitB(const float* __restrict__ Vv_T) {
    extern __shared__ unsigned char smraw[];
    __nv_bfloat16* stage = (__nv_bfloat16*)smraw;
    const int tid = threadIdx.x;
    const int v0 = blockIdx.x * 128;

    for (int idx = tid; idx < DD * 128; idx += 256) {
        int k = idx >> 7, c = idx & 127;
        int v = v0 + c;
        float val = (v < NV) ? Vv_T[(size_t)k * NV + v] : 0.f;
        __nv_bfloat16 hi = __float2bfloat16(val);
        __nv_bfloat16 lo = __float2bfloat16(val - __bfloat162float(hi));
        stage[c * 330 + k]       = hi;
        stage[c * 330 + 100 + k] = lo;
        stage[c * 330 + 200 + k] = hi;
    }
    for (int idx = tid; idx < 128 * 20; idx += 256) {
        int c = idx / 20, u = idx - c * 20;
        stage[c * 330 + 300 + u] = __float2bfloat16(0.f);
    }
    __syncthreads();
    const uint32_t* sg = (const uint32_t*)smraw;
    uint32_t* dst = (uint32_t*)g_Bcat;
    for (int e = tid; e < 128 * 160; e += 256) {
        int row = e / 160, u = e - row * 160;
        dst[(size_t)(v0 + row) * 160 + u] = sg[row * 165 + u];
    }
}

// -------- kernel 3: bf16 tensor GEMM + digitize + attn-weighted d-reduction --------
// grid (118, 8), 256 threads = 8 warps laid out 2(M) x 4(N), warp tile 64x64.
__device__ __forceinline__ void load_a_chunk(int b, int it2, uint32_t sAs, int tid) {
    int dc2 = it2 >> 2, kc2 = it2 & 3;
    const char* base = (const char*)g_Acat +
        ((size_t)(b * ND + dc2 * TILE_M)) * (K3 * 2) + (size_t)kc2 * (KC * 2);
    uint32_t dbase = sAs + (uint32_t)(it2 & 1) * AS_BYTES;
#pragma unroll 1
    for (int i = tid; i < TILE_M * 10; i += 256) {
        int row = i / 10, u = i - row * 10;
        cpa16(dbase + row * A_PITCH + u * 16, base + (size_t)row * (K3 * 2) + u * 16);
    }
}

__global__ void __launch_bounds__(256, 1)
k_main(const float* __restrict__ attn) {
    extern __shared__ unsigned char sm[];
    const uint32_t sBs   = smem_u32(sm);
    const uint32_t sAs   = sBs + BS_BYTES;
    float* attn_shf = (float*)(sm + BS_BYTES + 2 * AS_BYTES);
    float* vredf    = attn_shf + 128;

    const int tid  = threadIdx.x;
    const int lane = tid & 31, wid = tid >> 5;
    const int wm   = wid >> 2, wn = wid & 3;     // 2 x 4
    const int b    = blockIdx.y;
    const int v0   = blockIdx.x * TILE_N;

    const float binw_r = g_binw[lane & 15];

    // ---- prologue: B resident + first A chunk, one cp.async group ----
    {
        const char* bsrc = (const char*)g_Bcat + (size_t)v0 * (K3 * 2);
#pragma unroll 1
        for (int i = tid; i < TILE_N * 40; i += 256) {
            int row = i / 40, u = i - row * 40;
            cpa16(sBs + row * B_PITCH + u * 16, bsrc + (size_t)row * (K3 * 2) + u * 16);
        }
        load_a_chunk(b, 0, sAs, tid);
        cpa_commit();
    }

    float acc[4][8][4];
    float vcol[16];
#pragma unroll
    for (int j = 0; j < 16; j++) vcol[j] = 0.f;

    const int a_lm_row = (lane & 15);
    const int lm_koff  = ((lane >> 4) << 3);

#pragma unroll 1
    for (int it = 0; it < NDC * NKC; ++it) {
        const int dc = it >> 2, kc = it & 3;
        cpa_wait0();
        __syncthreads();
        if (kc == 0 && tid < 128)
            attn_shf[tid] = __ldg(&attn[b * ND + dc * TILE_M + tid]);
        if (it + 1 < NDC * NKC) { load_a_chunk(b, it + 1, sAs, tid); cpa_commit(); }

        const uint32_t sA_cur = sAs + (uint32_t)(it & 1) * AS_BYTES;

        if (kc == 0) {
#pragma unroll
            for (int mi = 0; mi < 4; mi++)
#pragma unroll
                for (int nj = 0; nj < 8; nj++)
#pragma unroll
                    for (int q = 0; q < 4; q++) acc[mi][nj][q] = 0.f;
        }

        // ---- 5 x k16 MMA steps on this K chunk ----
#pragma unroll
        for (int ks = 0; ks < KC / 16; ks++) {
            const int kl = ks * 16;
            const int kg = kc * KC + kl;
            uint32_t a[4][4];
#pragma unroll
            for (int mi = 0; mi < 4; mi++) {
                uint32_t addr = sA_cur + (wm * 64 + mi * 16 + a_lm_row) * A_PITCH
                              + (kl + lm_koff) * 2;
                ldm4(a[mi][0], a[mi][1], a[mi][2], a[mi][3], addr);
            }
            uint32_t bf[8][2];
#pragma unroll
            for (int nb = 0; nb < 4; nb++) {
                uint32_t addr = sBs + (wn * 64 + nb * 16 + a_lm_row) * B_PITCH
                              + (kg + lm_koff) * 2;
                uint32_t r0, r1, r2, r3;
                ldm4(r0, r1, r2, r3, addr);
                bf[nb * 2][0] = r0; bf[nb * 2][1] = r2;
                bf[nb * 2 + 1][0] = r1; bf[nb * 2 + 1][1] = r3;
            }
#pragma unroll
            for (int mi = 0; mi < 4; mi++)
#pragma unroll
                for (int nj = 0; nj < 8; nj++)
                    mma16816(acc[mi][nj], a[mi], bf[nj]);
        }

        // ---- epilogue per d-chunk: digitize -> shfl bin lookup -> attn-weighted acc ----
        if (kc == 3) {
#pragma unroll
            for (int mi = 0; mi < 4; mi++) {
#pragma unroll
                for (int gg = 0; gg < 2; gg++) {
                    float av = attn_shf[wm * 64 + mi * 16 + (lane >> 2) + gg * 8];
#pragma unroll
                    for (int nj = 0; nj < 8; nj++) {
#pragma unroll
                        for (int cc = 0; cc < 2; cc++) {
                            float s = acc[mi][nj][gg * 2 + cc];
                            int dig = __float2int_rd((s + 0.5f) * INV_STEP) + 1;
                            dig = dig < 0 ? 0 : (dig > 15 ? 15 : dig);
                            float w = __shfl_sync(0xffffffffu, binw_r, dig);
                            vcol[nj * 2 + cc] = fmaf(av, w, vcol[nj * 2 + cc]);
                        }
                    }
                }
            }
        }
    }

    // ---- reduce vcol over lanes sharing the same columns (lane>>2 groups) ----
#pragma unroll
    for (int j = 0; j < 16; j++) {
        vcol[j] += __shfl_down_sync(0xffffffffu, vcol[j], 16);
        vcol[j] += __shfl_down_sync(0xffffffffu, vcol[j], 8);
        vcol[j] += __shfl_down_sync(0xffffffffu, vcol[j], 4);
    }
    if (lane < 4) {
#pragma unroll
        for (int j = 0; j < 16; j++) {
            int nj = j >> 1, cc = j & 1;
            vredf[wid * 64 + nj * 8 + lane * 2 + cc] = vcol[j];
        }
    }
    __syncthreads();
    {
        int wn2 = tid >> 6, cl = tid & 63;
        float s = vredf[wn2 * 64 + cl] + vredf[(4 + wn2) * 64 + cl];
        g_weighted[b * NVP + v0 + wn2 * 64 + cl] = s;
    }
}

// -------- kernel 4: fused phi L1-norm + final GEMM --------
__global__ void __launch_bounds__(256)
k_final(const float* __restrict__ phi, float* __restrict__ out) {
    const int n0  = blockIdx.x * 4;
    const int tid = threadIdx.x;

    float acc[4][8];
    float l1[4];
#pragma unroll
    for (int r = 0; r < 4; r++) {
        l1[r] = 0.f;
#pragma unroll
        for (int bb = 0; bb < 8; bb++) acc[r][bb] = 0.f;
    }

    for (int base = tid * 4; base < NV; base += 1024) {
        float4 w[8];
#pragma unroll
        for (int bb = 0; bb < 8; bb++)
            w[bb] = *(const float4*)&g_weighted[bb * NVP + base];
#pragma unroll
        for (int r = 0; r < 4; r++) {
            float4 p = *(const float4*)&phi[(size_t)(n0 + r) * NV + base];
            l1[r] += fabsf(p.x) + fabsf(p.y) + fabsf(p.z) + fabsf(p.w);
#pragma unroll
            for (int bb = 0; bb < 8; bb++)
                acc[r][bb] += p.x * w[bb].x + p.y * w[bb].y + p.z * w[bb].z + p.w * w[bb].w;
        }
    }

    const unsigned mask = 0xffffffffu;
#pragma unroll
    for (int r = 0; r < 4; r++) {
#pragma unroll
        for (int bb = 0; bb < 8; bb++)
#pragma unroll
            for (int o = 16; o > 0; o >>= 1)
                acc[r][bb] += __shfl_down_sync(mask, acc[r][bb], o);
#pragma unroll
        for (int o = 16; o > 0; o >>= 1)
            l1[r] += __shfl_down_sync(mask, l1[r], o);
    }

    __shared__ float red[8][36];
    __shared__ float tot[36];
    const int wid = tid >> 5, lane = tid & 31;
    if (lane == 0) {
#pragma unroll
        for (int r = 0; r < 4; r++) {
#pragma unroll
            for (int bb = 0; bb < 8; bb++) red[wid][r * 9 + bb] = acc[r][bb];
            red[wid][r * 9 + 8] = l1[r];
        }
    }
    __syncthreads();
    if (tid < 36) {
        float s = 0.f;
#pragma unroll
        for (int w8 = 0; w8 < 8; w8++) s += red[w8][tid];
        tot[tid] = s;
    }
    __syncthreads();
    if (tid < 32) {
        int r  = tid >> 3;
        int bb = tid & 7;
        float l = tot[r * 9 + 8];
        out[bb * NC + (n0 + r)] = tot[r * 9 + bb] / fmaxf(l, 1e-12f);
    }
}

// -------- launcher --------
extern "C" void kernel_launch(void* const* d_in, const int* in_sizes, int n_in,
                              void* d_out, int out_size) {
    const int*   doc_index = (const int*)d_in[0];
    const float* attn      = (const float*)d_in[1];
    const float* emb       = (const float*)d_in[2];
    const float* vvt       = (const float*)d_in[3];
    const float* phi       = (const float*)d_in[4];
    const float* diff      = (const float*)d_in[5];
    const float* start     = (const float*)d_in[6];
    float* out = (float*)d_out;

    k_binw<<<1, 32>>>(diff, start);

    k_splitA<<<(NB * ND * K3 + 255) / 256, 256>>>(doc_index, emb);

    cudaFuncSetAttribute(k_splitB, cudaFuncAttributeMaxDynamicSharedMemorySize, 128 * 660);
    k_splitB<<<NVP / 128, 256, 128 * 660>>>(vvt);

    cudaFuncSetAttribute(k_main, cudaFuncAttributeMaxDynamicSharedMemorySize, SMEM_MAIN);
    dim3 grid(N_VT, NB);
    k_main<<<grid, 256, SMEM_MAIN>>>(attn);

    k_final<<<NC / 4, 256>>>(phi, out);
}

// round 3
// speedup vs baseline: 5.4689x; 2.0985x over previous
#include <cuda_runtime.h>
#include <cuda_bf16.h>
#include <cstdint>

#define NB   8
#define ND   1024
#define DD   100
#define NV   30000
#define NC   512

#define K1   112              // 100 + 12 zero pad (7 x k16)
#define NVP  30208            // 118 * 256
#define TILE_N 256
#define TILE_M 128
#define N_VT (NVP / TILE_N)   // 118
#define NDC  (ND / TILE_M)    // 8

#define PITCH 240             // 15 x 16B, odd units -> conflict-free ldmatrix
#define ABUF  (TILE_M * PITCH)            // 30720
#define BBUF  (TILE_N * PITCH)            // 61440
#define SMEM_MAIN (BBUF + 2*ABUF + 16*64*4)  // 126976

#define INV_STEP (14.0f / 1.49f)

// -------- device scratch --------
__device__ __nv_bfloat16 g_A[(size_t)NB * ND * K1];   // [row][k] row-major, 224B rows
__device__ __nv_bfloat16 g_B[(size_t)NVP * K1];       // [v][k]
__device__ float g_weighted[NB * NVP];
__device__ float g_binw[16];

// -------- helpers --------
__device__ __forceinline__ uint32_t smem_u32(const void* p) {
    return (uint32_t)__cvta_generic_to_shared(p);
}
__device__ __forceinline__ void cpa16(uint32_t dst, const void* src) {
    asm volatile("cp.async.cg.shared.global [%0], [%1], 16;" :: "r"(dst), "l"(src));
}
__device__ __forceinline__ void cpa_commit() { asm volatile("cp.async.commit_group;"); }
__device__ __forceinline__ void cpa_wait0()  { asm volatile("cp.async.wait_group 0;"); }

__device__ __forceinline__ void ldm4(uint32_t& r0, uint32_t& r1, uint32_t& r2, uint32_t& r3,
                                     uint32_t addr) {
    asm volatile("ldmatrix.sync.aligned.m8n8.x4.shared.b16 {%0,%1,%2,%3}, [%4];"
                 : "=r"(r0), "=r"(r1), "=r"(r2), "=r"(r3) : "r"(addr));
}
__device__ __forceinline__ void mma16816(float* c, const uint32_t* a, const uint32_t* b) {
    asm volatile(
        "mma.sync.aligned.m16n8k16.row.col.f32.bf16.bf16.f32 "
        "{%0,%1,%2,%3}, {%4,%5,%6,%7}, {%8,%9}, {%0,%1,%2,%3};"
        : "+f"(c[0]), "+f"(c[1]), "+f"(c[2]), "+f"(c[3])
        : "r"(a[0]), "r"(a[1]), "r"(a[2]), "r"(a[3]), "r"(b[0]), "r"(b[1]));
}

// -------- kernel 0: bin weights --------
__global__ void k_binw(const float* __restrict__ diff, const float* __restrict__ start) {
    if (threadIdx.x == 0) {
        float acc = start[0];
        for (int j = 0; j < 16; j++) {
            float d = diff[j];
            acc += d > 0.f ? d : 0.f;
            g_binw[j] = acc;
        }
    }
}

// -------- kernel 1: gather + bf16 cast of A rows --------
__global__ void k_prepA(const int* __restrict__ doc_index, const float* __restrict__ emb) {
    int e = blockIdx.x * blockDim.x + threadIdx.x;
    if (e >= NB * ND * K1) return;
    int r = e / K1;
    int k = e - r * K1;
    float val = (k < DD) ? emb[(size_t)doc_index[r] * DD + k] : 0.f;
    g_A[e] = __float2bfloat16(val);
}

// -------- kernel 2: transpose + bf16 cast of B --------
// block handles 128 v columns; smem staging pitch 120 bf16 (60 words)
__global__ void k_prepB(const float* __restrict__ Vv_T) {
    __shared__ __nv_bfloat16 stage[128 * 120];
    const int tid = threadIdx.x;
    const int v0 = blockIdx.x * 128;

    for (int idx = tid; idx < DD * 128; idx += 256) {
        int k = idx >> 7, c = idx & 127;
        int v = v0 + c;
        float val = (v < NV) ? Vv_T[(size_t)k * NV + v] : 0.f;
        stage[c * 120 + k] = __float2bfloat16(val);
    }
    for (int idx = tid; idx < 128 * 12; idx += 256) {
        int c = idx / 12, u = idx - c * 12;
        stage[c * 120 + DD + u] = __float2bfloat16(0.f);
    }
    __syncthreads();
    const uint32_t* sg = (const uint32_t*)stage;
    uint32_t* dst = (uint32_t*)g_B;
    for (int e = tid; e < 128 * 56; e += 256) {
        int row = e / 56, u = e - row * 56;
        dst[(size_t)(v0 + row) * 56 + u] = sg[row * 60 + u];
    }
}

// -------- kernel 3: bf16 tensor GEMM + digitize + attn-weighted d-reduction --------
// grid (118, 8), 512 threads = 16 warps 4(M) x 4(N); warp tile 32 x 64.
__device__ __forceinline__ void load_a_chunk(int b, int dc, uint32_t dbase, int tid) {
    const char* base = (const char*)g_A + ((size_t)(b * ND + dc * TILE_M)) * (K1 * 2);
#pragma unroll 1
    for (int i = tid; i < TILE_M * 14; i += 512) {
        int row = i / 14, u = i - row * 14;
        cpa16(dbase + row * PITCH + u * 16, base + (size_t)row * (K1 * 2) + u * 16);
    }
}

__global__ void __launch_bounds__(512, 1)
k_main(const float* __restrict__ attn) {
    extern __shared__ unsigned char sm[];
    const uint32_t sBs = smem_u32(sm);
    const uint32_t sAs = sBs + BBUF;
    float* vred = (float*)(sm + BBUF + 2 * ABUF);

    const int tid  = threadIdx.x;
    const int lane = tid & 31, wid = tid >> 5;
    const int wm   = wid >> 2, wn = wid & 3;      // 4 x 4 warps
    const int b    = blockIdx.y;
    const int v0   = blockIdx.x * TILE_N;

    const float binw_r = __ldg(&g_binw[lane & 15]);
    const int lm_row  = lane & 15;
    const int lm_koff = (lane >> 4) << 3;

    // ---- prologue: B resident + first A chunk ----
    {
        const char* bsrc = (const char*)g_B + (size_t)v0 * (K1 * 2);
#pragma unroll 1
        for (int i = tid; i < TILE_N * 14; i += 512) {
            int row = i / 14, u = i - row * 14;
            cpa16(sBs + row * PITCH + u * 16, bsrc + (size_t)row * (K1 * 2) + u * 16);
        }
        load_a_chunk(b, 0, sAs, tid);
        cpa_commit();
    }

    float vcol[16];
#pragma unroll
    for (int j = 0; j < 16; j++) vcol[j] = 0.f;

    const float* attn_b = attn + b * ND;

#pragma unroll 1
    for (int dc = 0; dc < NDC; ++dc) {
        cpa_wait0();
        __syncthreads();
        if (dc + 1 < NDC) {
            load_a_chunk(b, dc + 1, sAs + (uint32_t)((dc + 1) & 1) * ABUF, tid);
            cpa_commit();
        }
        const uint32_t sA = sAs + (uint32_t)(dc & 1) * ABUF;

        float acc[2][8][4];
#pragma unroll
        for (int mi = 0; mi < 2; mi++)
#pragma unroll
            for (int nj = 0; nj < 8; nj++)
#pragma unroll
                for (int q = 0; q < 4; q++) acc[mi][nj][q] = 0.f;

        // ---- 7 x k16 MMA steps ----
#pragma unroll
        for (int ks = 0; ks < K1 / 16; ks++) {
            const int kl = ks * 16;
            uint32_t a[2][4];
#pragma unroll
            for (int mi = 0; mi < 2; mi++) {
                uint32_t addr = sA + (wm * 32 + mi * 16 + lm_row) * PITCH
                              + (kl + lm_koff) * 2;
                ldm4(a[mi][0], a[mi][1], a[mi][2], a[mi][3], addr);
            }
            uint32_t bf[8][2];
#pragma unroll
            for (int nb = 0; nb < 4; nb++) {
                uint32_t addr = sBs + (wn * 64 + nb * 16 + lm_row) * PITCH
                              + (kl + lm_koff) * 2;
                uint32_t r0, r1, r2, r3;
                ldm4(r0, r1, r2, r3, addr);
                bf[nb * 2][0] = r0;     bf[nb * 2][1] = r2;
                bf[nb * 2 + 1][0] = r1; bf[nb * 2 + 1][1] = r3;
            }
#pragma unroll
            for (int mi = 0; mi < 2; mi++)
#pragma unroll
                for (int nj = 0; nj < 8; nj++)
                    mma16816(acc[mi][nj], a[mi], bf[nj]);
        }

        // ---- epilogue: digitize -> shfl bin lookup -> attn-weighted acc ----
        const int rbase = dc * TILE_M + wm * 32 + (lane >> 2);
#pragma unroll
        for (int mi = 0; mi < 2; mi++) {
#pragma unroll
            for (int gg = 0; gg < 2; gg++) {
                float av = __ldg(&attn_b[rbase + mi * 16 + gg * 8]);
#pragma unroll
                for (int nj = 0; nj < 8; nj++) {
#pragma unroll
                    for (int cc = 0; cc < 2; cc++) {
                        float s = acc[mi][nj][gg * 2 + cc];
                        int dig = __float2int_rd((s + 0.5f) * INV_STEP) + 1;
                        dig = dig < 0 ? 0 : (dig > 15 ? 15 : dig);
                        float w = __shfl_sync(0xffffffffu, binw_r, dig);
                        vcol[nj * 2 + cc] = fmaf(av, w, vcol[nj * 2 + cc]);
                    }
                }
            }
        }
    }

    // ---- reduce vcol over lanes sharing the same columns ----
#pragma unroll
    for (int j = 0; j < 16; j++) {
        vcol[j] += __shfl_down_sync(0xffffffffu, vcol[j], 16);
        vcol[j] += __shfl_down_sync(0xffffffffu, vcol[j], 8);
        vcol[j] += __shfl_down_sync(0xffffffffu, vcol[j], 4);
    }
    if (lane < 4) {
#pragma unroll
        for (int j = 0; j < 16; j++) {
            int nj = j >> 1, cc = j & 1;
            vred[wid * 64 + nj * 8 + lane * 2 + cc] = vcol[j];
        }
    }
    __syncthreads();
    if (tid < TILE_N) {
        int wn2 = tid >> 6, cl = tid & 63;
        float s = 0.f;
#pragma unroll
        for (int wm2 = 0; wm2 < 4; wm2++) s += vred[(wm2 * 4 + wn2) * 64 + cl];
        g_weighted[b * NVP + v0 + tid] = s;
    }
}

// -------- kernel 4: fused phi L1-norm + final GEMM --------
__global__ void __launch_bounds__(256)
k_final(const float* __restrict__ phi, float* __restrict__ out) {
    const int n0  = blockIdx.x * 4;
    const int tid = threadIdx.x;

    float acc[4][8];
    float l1[4];
#pragma unroll
    for (int r = 0; r < 4; r++) {
        l1[r] = 0.f;
#pragma unroll
        for (int bb = 0; bb < 8; bb++) acc[r][bb] = 0.f;
    }

    for (int base = tid * 4; base < NV; base += 1024) {
        float4 w[8];
#pragma unroll
        for (int bb = 0; bb < 8; bb++)
            w[bb] = *(const float4*)&g_weighted[bb * NVP + base];
#pragma unroll
        for (int r = 0; r < 4; r++) {
            float4 p = *(const float4*)&phi[(size_t)(n0 + r) * NV + base];
            l1[r] += fabsf(p.x) + fabsf(p.y) + fabsf(p.z) + fabsf(p.w);
#pragma unroll
            for (int bb = 0; bb < 8; bb++)
                acc[r][bb] += p.x * w[bb].x + p.y * w[bb].y + p.z * w[bb].z + p.w * w[bb].w;
        }
    }

    const unsigned mask = 0xffffffffu;
#pragma unroll
    for (int r = 0; r < 4; r++) {
#pragma unroll
        for (int bb = 0; bb < 8; bb++)
#pragma unroll
            for (int o = 16; o > 0; o >>= 1)
                acc[r][bb] += __shfl_down_sync(mask, acc[r][bb], o);
#pragma unroll
        for (int o = 16; o > 0; o >>= 1)
            l1[r] += __shfl_down_sync(mask, l1[r], o);
    }

    __shared__ float red[8][36];
    __shared__ float tot[36];
    const int wid = tid >> 5, lane = tid & 31;
    if (lane == 0) {
#pragma unroll
        for (int r = 0; r < 4; r++) {
#pragma unroll
            for (int bb = 0; bb < 8; bb++) red[wid][r * 9 + bb] = acc[r][bb];
            red[wid][r * 9 + 8] = l1[r];
        }
    }
    __syncthreads();
    if (tid < 36) {
        float s = 0.f;
#pragma unroll
        for (int w8 = 0; w8 < 8; w8++) s += red[w8][tid];
        tot[tid] = s;
    }
    __syncthreads();
    if (tid < 32) {
        int r  = tid >> 3;
        int bb = tid & 7;
        float l = tot[r * 9 + 8];
        out[bb * NC + (n0 + r)] = tot[r * 9 + bb] / fmaxf(l, 1e-12f);
    }
}

// -------- launcher --------
extern "C" void kernel_launch(void* const* d_in, const int* in_sizes, int n_in,
                              void* d_out, int out_size) {
    const int*   doc_index = (const int*)d_in[0];
    const float* attn      = (const float*)d_in[1];
    const float* emb       = (const float*)d_in[2];
    const float* vvt       = (const float*)d_in[3];
    const float* phi       = (const float*)d_in[4];
    const float* diff      = (const float*)d_in[5];
    const float* start     = (const float*)d_in[6];
    float* out = (float*)d_out;

    k_binw<<<1, 32>>>(diff, start);

    k_prepA<<<(NB * ND * K1 + 511) / 512, 512>>>(doc_index, emb);

    k_prepB<<<NVP / 128, 256>>>(vvt);

    cudaFuncSetAttribute(k_main, cudaFuncAttributeMaxDynamicSharedMemorySize, SMEM_MAIN);
    dim3 grid(N_VT, NB);
    k_main<<<grid, 512, SMEM_MAIN>>>(attn);

    k_final<<<NC / 4, 256>>>(phi, out);
}

// round 5
// speedup vs baseline: 7.1764x; 1.3122x over previous
#include <cuda_runtime.h>
#include <cuda_bf16.h>
#include <cstdint>

#define NB   8
#define ND   1024
#define DD   100
#define NV   30000
#define NC   512

#define K1   112              // 100 + 12 zero pad (7 x k16)
#define NVP  30208            // 118 * 256
#define TILE_N 256
#define TILE_M 64
#define N_VT (NVP / TILE_N)   // 118
#define NDC  8                // 8 chunks of 64 rows = 512 rows per CTA (half of ND)

#define PITCH 240             // 15 x 16B, odd units -> conflict-free ldmatrix
#define ABUF  (TILE_M * PITCH)               // 15360
#define BBUF  (TILE_N * PITCH)               // 61440
#define SMEM_MAIN (BBUF + 2*ABUF + 8*64*4)   // 94208

#define INV_STEP (14.0f / 1.49f)

// -------- device scratch --------
__device__ __nv_bfloat16 g_A[(size_t)NB * ND * K1];     // [row][k] row-major, 224B rows
__device__ __nv_bfloat16 g_B[(size_t)NVP * K1];         // [v][k]
__device__ float g_weighted[16 * NVP];                  // row = mc*8 + b
__device__ float g_binw[16];
__device__ float g_part[4 * 128 * 36];

// -------- helpers --------
__device__ __forceinline__ uint32_t smem_u32(const void* p) {
    return (uint32_t)__cvta_generic_to_shared(p);
}
__device__ __forceinline__ void cpa16(uint32_t dst, const void* src) {
    asm volatile("cp.async.cg.shared.global [%0], [%1], 16;" :: "r"(dst), "l"(src));
}
__device__ __forceinline__ void cpa_commit() { asm volatile("cp.async.commit_group;"); }
__device__ __forceinline__ void cpa_wait0()  { asm volatile("cp.async.wait_group 0;"); }

__device__ __forceinline__ void ldm4(uint32_t& r0, uint32_t& r1, uint32_t& r2, uint32_t& r3,
                                     uint32_t addr) {
    asm volatile("ldmatrix.sync.aligned.m8n8.x4.shared.b16 {%0,%1,%2,%3}, [%4];"
                 : "=r"(r0), "=r"(r1), "=r"(r2), "=r"(r3) : "r"(addr));
}
__device__ __forceinline__ void mma16816(float* c, const uint32_t* a, const uint32_t* b) {
    asm volatile(
        "mma.sync.aligned.m16n8k16.row.col.f32.bf16.bf16.f32 "
        "{%0,%1,%2,%3}, {%4,%5,%6,%7}, {%8,%9}, {%0,%1,%2,%3};"
        : "+f"(c[0]), "+f"(c[1]), "+f"(c[2]), "+f"(c[3])
        : "r"(a[0]), "r"(a[1]), "r"(a[2]), "r"(a[3]), "r"(b[0]), "r"(b[1]));
}
__device__ __forceinline__ float fma_sat(float a, float b, float c) {
    float d;
    asm("fma.rn.sat.f32 %0, %1, %2, %3;" : "=f"(d) : "f"(a), "f"(b), "f"(c));
    return d;
}

// -------- kernel 0: bin weights --------
__global__ void k_binw(const float* __restrict__ diff, const float* __restrict__ start) {
    if (threadIdx.x == 0) {
        float acc = start[0];
        for (int j = 0; j < 16; j++) {
            float d = diff[j];
            acc += d > 0.f ? d : 0.f;
            g_binw[j] = acc;
        }
    }
}

// -------- kernel 1: gather + bf16 cast of A rows --------
__global__ void k_prepA(const int* __restrict__ doc_index, const float* __restrict__ emb) {
    int e = blockIdx.x * blockDim.x + threadIdx.x;
    if (e >= NB * ND * K1) return;
    int r = e / K1;
    int k = e - r * K1;
    float val = (k < DD) ? emb[(size_t)doc_index[r] * DD + k] : 0.f;
    g_A[e] = __float2bfloat16(val);
}

// -------- kernel 2: transpose + bf16 cast of B --------
__global__ void k_prepB(const float* __restrict__ Vv_T) {
    __shared__ __nv_bfloat16 stage[128 * 120];
    const int tid = threadIdx.x;
    const int v0 = blockIdx.x * 128;

    for (int idx = tid; idx < DD * 128; idx += 256) {
        int k = idx >> 7, c = idx & 127;
        int v = v0 + c;
        float val = (v < NV) ? Vv_T[(size_t)k * NV + v] : 0.f;
        stage[c * 120 + k] = __float2bfloat16(val);
    }
    for (int idx = tid; idx < 128 * 12; idx += 256) {
        int c = idx / 12, u = idx - c * 12;
        stage[c * 120 + DD + u] = __float2bfloat16(0.f);
    }
    __syncthreads();
    const uint32_t* sg = (const uint32_t*)stage;
    uint32_t* dst = (uint32_t*)g_B;
    for (int e = tid; e < 128 * 56; e += 256) {
        int row = e / 56, u = e - row * 56;
        dst[(size_t)(v0 + row) * 56 + u] = sg[row * 60 + u];
    }
}

// -------- kernel 3: bf16 tensor GEMM + digitize + attn-weighted d-reduction --------
// grid (118, 16): blockIdx.y = b*2 + mc; 256 threads = 8 warps 2(M) x 4(N); warp tile 32x64.
// 2 CTAs / SM for cross-CTA latency overlap.
__device__ __forceinline__ void load_a_chunk(int rowbase, int dc, uint32_t dbase, int tid) {
    const char* base = (const char*)g_A + ((size_t)(rowbase + dc * TILE_M)) * (K1 * 2);
#pragma unroll 1
    for (int i = tid; i < TILE_M * 14; i += 256) {
        int row = i / 14, u = i - row * 14;
        cpa16(dbase + row * PITCH + u * 16, base + (size_t)row * (K1 * 2) + u * 16);
    }
}

__global__ void __launch_bounds__(256, 2)
k_main(const float* __restrict__ attn) {
    extern __shared__ unsigned char sm[];
    const uint32_t sBs = smem_u32(sm);
    const uint32_t sAs = sBs + BBUF;
    float* vred = (float*)(sm + BBUF + 2 * ABUF);

    const int tid  = threadIdx.x;
    const int lane = tid & 31, wid = tid >> 5;
    const int wm   = wid >> 2, wn = wid & 3;      // 2 x 4 warps
    const int by   = blockIdx.y;
    const int b    = by >> 1;
    const int mc   = by & 1;
    const int rowbase = b * ND + mc * 512;
    const int v0   = blockIdx.x * TILE_N;

    const float binw_r = __ldg(&g_binw[lane & 15]);
    const int lm_row  = lane & 15;
    const int lm_koff = (lane >> 4) << 3;

    // digitize constants: dig = trunc(clamp((s+0.5)*INV + 1, 0, 15))
    const float S2 = INV_STEP / 15.0f;
    const float C2 = (0.5f * INV_STEP + 1.0f) / 15.0f;

    // ---- prologue: B resident + first A chunk ----
    {
        const char* bsrc = (const char*)g_B + (size_t)v0 * (K1 * 2);
#pragma unroll 1
        for (int i = tid; i < TILE_N * 14; i += 256) {
            int row = i / 14, u = i - row * 14;
            cpa16(sBs + row * PITCH + u * 16, bsrc + (size_t)row * (K1 * 2) + u * 16);
        }
        load_a_chunk(rowbase, 0, sAs, tid);
        cpa_commit();
    }

    float vcol[16];
#pragma unroll
    for (int j = 0; j < 16; j++) vcol[j] = 0.f;

    const float* attn_b = attn + rowbase;

#pragma unroll 1
    for (int dc = 0; dc < NDC; ++dc) {
        cpa_wait0();
        __syncthreads();
        if (dc + 1 < NDC) {
            load_a_chunk(rowbase, dc + 1, sAs + (uint32_t)((dc + 1) & 1) * ABUF, tid);
            cpa_commit();
        }
        const uint32_t sA = sAs + (uint32_t)(dc & 1) * ABUF;

        // prefetch the 4 attn values used in this dc's epilogue
        const int arow = dc * TILE_M + wm * 32 + (lane >> 2);
        float av[2][2];
#pragma unroll
        for (int mi = 0; mi < 2; mi++)
#pragma unroll
            for (int gg = 0; gg < 2; gg++)
                av[mi][gg] = __ldg(&attn_b[arow + mi * 16 + gg * 8]);

        float acc[2][8][4];
#pragma unroll
        for (int mi = 0; mi < 2; mi++)
#pragma unroll
            for (int nj = 0; nj < 8; nj++)
#pragma unroll
                for (int q = 0; q < 4; q++) acc[mi][nj][q] = 0.f;

        // ---- 7 x k16 MMA steps ----
#pragma unroll
        for (int ks = 0; ks < K1 / 16; ks++) {
            const int kl = ks * 16;
            uint32_t a[2][4];
#pragma unroll
            for (int mi = 0; mi < 2; mi++) {
                uint32_t addr = sA + (wm * 32 + mi * 16 + lm_row) * PITCH
                              + (kl + lm_koff) * 2;
                ldm4(a[mi][0], a[mi][1], a[mi][2], a[mi][3], addr);
            }
            uint32_t bf[8][2];
#pragma unroll
            for (int nb = 0; nb < 4; nb++) {
                uint32_t addr = sBs + (wn * 64 + nb * 16 + lm_row) * PITCH
                              + (kl + lm_koff) * 2;
                uint32_t r0, r1, r2, r3;
                ldm4(r0, r1, r2, r3, addr);
                bf[nb * 2][0] = r0;     bf[nb * 2][1] = r2;
                bf[nb * 2 + 1][0] = r1; bf[nb * 2 + 1][1] = r3;
            }
#pragma unroll
            for (int mi = 0; mi < 2; mi++)
#pragma unroll
                for (int nj = 0; nj < 8; nj++)
                    mma16816(acc[mi][nj], a[mi], bf[nj]);
        }

        // ---- epilogue: sat-digitize -> shfl bin lookup -> attn-weighted acc ----
#pragma unroll
        for (int mi = 0; mi < 2; mi++) {
#pragma unroll
            for (int gg = 0; gg < 2; gg++) {
                const float a_v = av[mi][gg];
#pragma unroll
                for (int nj = 0; nj < 8; nj++) {
#pragma unroll
                    for (int cc = 0; cc < 2; cc++) {
                        float s = acc[mi][nj][gg * 2 + cc];
                        float y = fma_sat(s, S2, C2);        // clamp(t,0,15)/15
                        int dig = __float2int_rz(y * 15.0f); // trunc
                        float w = __shfl_sync(0xffffffffu, binw_r, dig);
                        vcol[nj * 2 + cc] = fmaf(a_v, w, vcol[nj * 2 + cc]);
                    }
                }
            }
        }
    }

    // ---- reduce vcol over lanes sharing the same columns ----
#pragma unroll
    for (int j = 0; j < 16; j++) {
        vcol[j] += __shfl_down_sync(0xffffffffu, vcol[j], 16);
        vcol[j] += __shfl_down_sync(0xffffffffu, vcol[j], 8);
        vcol[j] += __shfl_down_sync(0xffffffffu, vcol[j], 4);
    }
    if (lane < 4) {
#pragma unroll
        for (int j = 0; j < 16; j++) {
            int nj = j >> 1, cc = j & 1;
            vred[wid * 64 + nj * 8 + lane * 2 + cc] = vcol[j];
        }
    }
    __syncthreads();
    {
        int wn2 = tid >> 6, cl = tid & 63;
        float s = vred[wn2 * 64 + cl] + vred[(4 + wn2) * 64 + cl];
        g_weighted[(size_t)(mc * 8 + b) * NVP + v0 + tid] = s;
    }
}

// -------- kernel 4a: phi L1 + partial dots over NV chunks --------
#define CHV 7552   // NVP/4
__global__ void __launch_bounds__(256)
k_fin1(const float* __restrict__ phi) {
    const int rb  = blockIdx.x;          // 0..127 (4 concept rows each)
    const int sp  = blockIdx.y;          // 0..3   (NV chunk)
    const int n0  = rb * 4;
    const int tid = threadIdx.x;

    const int vbeg = sp * CHV;
    const int vend = (vbeg + CHV < NV) ? vbeg + CHV : NV;

    float acc[4][8];
    float l1[4];
#pragma unroll
    for (int r = 0; r < 4; r++) {
        l1[r] = 0.f;
#pragma unroll
        for (int bb = 0; bb < 8; bb++) acc[r][bb] = 0.f;
    }

    for (int base = vbeg + tid * 4; base < vend; base += 1024) {
        float4 w[8];
#pragma unroll
        for (int bb = 0; bb < 8; bb++) {
            float4 w0 = *(const float4*)&g_weighted[(size_t)bb * NVP + base];
            float4 w1 = *(const float4*)&g_weighted[(size_t)(8 + bb) * NVP + base];
            w[bb].x = w0.x + w1.x; w[bb].y = w0.y + w1.y;
            w[bb].z = w0.z + w1.z; w[bb].w = w0.w + w1.w;
        }
#pragma unroll
        for (int r = 0; r < 4; r++) {
            float4 p = *(const float4*)&phi[(size_t)(n0 + r) * NV + base];
            l1[r] += fabsf(p.x) + fabsf(p.y) + fabsf(p.z) + fabsf(p.w);
#pragma unroll
            for (int bb = 0; bb < 8; bb++)
                acc[r][bb] += p.x * w[bb].x + p.y * w[bb].y + p.z * w[bb].z + p.w * w[bb].w;
        }
    }

    const unsigned mask = 0xffffffffu;
#pragma unroll
    for (int r = 0; r < 4; r++) {
#pragma unroll
        for (int bb = 0; bb < 8; bb++)
#pragma unroll
            for (int o = 16; o > 0; o >>= 1)
                acc[r][bb] += __shfl_down_sync(mask, acc[r][bb], o);
#pragma unroll
        for (int o = 16; o > 0; o >>= 1)
            l1[r] += __shfl_down_sync(mask, l1[r], o);
    }

    __shared__ float red[8][36];
    const int wid = tid >> 5, lane = tid & 31;
    if (lane == 0) {
#pragma unroll
        for (int r = 0; r < 4; r++) {
#pragma unroll
            for (int bb = 0; bb < 8; bb++) red[wid][r * 9 + bb] = acc[r][bb];
            red[wid][r * 9 + 8] = l1[r];
        }
    }
    __syncthreads();
    if (tid < 36) {
        float s = 0.f;
#pragma unroll
        for (int w8 = 0; w8 < 8; w8++) s += red[w8][tid];
        g_part[(sp * 128 + rb) * 36 + tid] = s;
    }
}

// -------- kernel 4b: combine partials + normalize + write output --------
__global__ void __launch_bounds__(64)
k_fin2(float* __restrict__ out) {
    const int rb  = blockIdx.x;
    const int tid = threadIdx.x;
    __shared__ float tot[36];
    if (tid < 36) {
        float s = 0.f;
#pragma unroll
        for (int sp = 0; sp < 4; sp++) s += g_part[(sp * 128 + rb) * 36 + tid];
        tot[tid] = s;
    }
    __syncthreads();
    if (tid < 32) {
        int r  = tid >> 3;
        int bb = tid & 7;
        float l = tot[r * 9 + 8];
        out[bb * NC + (rb * 4 + r)] = tot[r * 9 + bb] / fmaxf(l, 1e-12f);
    }
}

// -------- launcher --------
extern "C" void kernel_launch(void* const* d_in, const int* in_sizes, int n_in,
                              void* d_out, int out_size) {
    const int*   doc_index = (const int*)d_in[0];
    const float* attn      = (const float*)d_in[1];
    const float* emb       = (const float*)d_in[2];
    const float* vvt       = (const float*)d_in[3];
    const float* phi       = (const float*)d_in[4];
    const float* diff      = (const float*)d_in[5];
    const float* start     = (const float*)d_in[6];
    float* out = (float*)d_out;

    k_binw<<<1, 32>>>(diff, start);

    k_prepA<<<(NB * ND * K1 + 511) / 512, 512>>>(doc_index, emb);
    k_prepB<<<NVP / 128, 256>>>(vvt);

    cudaFuncSetAttribute(k_main, cudaFuncAttributeMaxDynamicSharedMemorySize, SMEM_MAIN);
    dim3 grid(N_VT, NB * 2);
    k_main<<<grid, 256, SMEM_MAIN>>>(attn);

    dim3 g1(128, 4);
    k_fin1<<<g1, 256>>>(phi);
    k_fin2<<<128, 64>>>(out);
}

// round 6
// speedup vs baseline: 7.5116x; 1.0467x over previous
#include <cuda_runtime.h>
#include <cuda_bf16.h>
#include <cstdint>

#define NB   8
#define ND   1024
#define DD   100
#define NV   30000
#define NC   512

#define K1   112              // 100 + 12 zero pad (7 x k16)
#define NVP  30208            // 118 * 256
#define TILE_N 256
#define TILE_M 64
#define N_VT (NVP / TILE_N)   // 118
#define NDC  8                // 8 chunks of 64 rows = 512 rows per CTA (half of ND)

#define PITCH 240             // 15 x 16B, odd units -> conflict-free ldmatrix
#define ABUF  (TILE_M * PITCH)               // 15360
#define BBUF  (TILE_N * PITCH)               // 61440
#define NSTAGE 3
#define SMEM_MAIN (BBUF + NSTAGE*ABUF + 8*64*4)   // 109568

#define INV_STEP (14.0f / 1.49f)

// -------- device scratch --------
__device__ __nv_bfloat16 g_A[(size_t)NB * ND * K1];     // [row][k] row-major, 224B rows
__device__ __nv_bfloat16 g_B[(size_t)NVP * K1];         // [v][k]
__device__ float g_weighted[16 * NVP];                  // row = mc*8 + b
__device__ float g_binw[16];
__device__ float g_part[4 * 128 * 36];

// -------- helpers --------
__device__ __forceinline__ uint32_t smem_u32(const void* p) {
    return (uint32_t)__cvta_generic_to_shared(p);
}
__device__ __forceinline__ void cpa16(uint32_t dst, const void* src) {
    asm volatile("cp.async.cg.shared.global [%0], [%1], 16;" :: "r"(dst), "l"(src));
}
__device__ __forceinline__ void cpa_commit() { asm volatile("cp.async.commit_group;"); }

__device__ __forceinline__ void ldm4(uint32_t& r0, uint32_t& r1, uint32_t& r2, uint32_t& r3,
                                     uint32_t addr) {
    asm volatile("ldmatrix.sync.aligned.m8n8.x4.shared.b16 {%0,%1,%2,%3}, [%4];"
                 : "=r"(r0), "=r"(r1), "=r"(r2), "=r"(r3) : "r"(addr));
}
__device__ __forceinline__ void mma16816(float* c, const uint32_t* a, const uint32_t* b) {
    asm volatile(
        "mma.sync.aligned.m16n8k16.row.col.f32.bf16.bf16.f32 "
        "{%0,%1,%2,%3}, {%4,%5,%6,%7}, {%8,%9}, {%0,%1,%2,%3};"
        : "+f"(c[0]), "+f"(c[1]), "+f"(c[2]), "+f"(c[3])
        : "r"(a[0]), "r"(a[1]), "r"(a[2]), "r"(a[3]), "r"(b[0]), "r"(b[1]));
}
__device__ __forceinline__ float fma_sat(float a, float b, float c) {
    float d;
    asm("fma.rn.sat.f32 %0, %1, %2, %3;" : "=f"(d) : "f"(a), "f"(b), "f"(c));
    return d;
}
// shfl.idx taking raw bits as lane index (b[4:0] used; magic guarantees low bits = dig)
__device__ __forceinline__ float shfl_idx_raw(float v, uint32_t idx) {
    float r;
    asm volatile("shfl.sync.idx.b32 %0, %1, %2, 0x1f, 0xffffffff;"
                 : "=f"(r) : "f"(v), "r"(idx));
    return r;
}

// -------- kernel 0: bin weights --------
__global__ void k_binw(const float* __restrict__ diff, const float* __restrict__ start) {
    if (threadIdx.x == 0) {
        float acc = start[0];
        for (int j = 0; j < 16; j++) {
            float d = diff[j];
            acc += d > 0.f ? d : 0.f;
            g_binw[j] = acc;
        }
    }
}

// -------- kernel 1: gather + bf16 cast of A rows --------
__global__ void k_prepA(const int* __restrict__ doc_index, const float* __restrict__ emb) {
    int e = blockIdx.x * blockDim.x + threadIdx.x;
    if (e >= NB * ND * K1) return;
    int r = e / K1;
    int k = e - r * K1;
    float val = (k < DD) ? emb[(size_t)doc_index[r] * DD + k] : 0.f;
    g_A[e] = __float2bfloat16(val);
}

// -------- kernel 2: transpose + bf16 cast of B --------
__global__ void k_prepB(const float* __restrict__ Vv_T) {
    __shared__ __nv_bfloat16 stage[128 * 120];
    const int tid = threadIdx.x;
    const int v0 = blockIdx.x * 128;

    for (int idx = tid; idx < DD * 128; idx += 256) {
        int k = idx >> 7, c = idx & 127;
        int v = v0 + c;
        float val = (v < NV) ? Vv_T[(size_t)k * NV + v] : 0.f;
        stage[c * 120 + k] = __float2bfloat16(val);
    }
    for (int idx = tid; idx < 128 * 12; idx += 256) {
        int c = idx / 12, u = idx - c * 12;
        stage[c * 120 + DD + u] = __float2bfloat16(0.f);
    }
    __syncthreads();
    const uint32_t* sg = (const uint32_t*)stage;
    uint32_t* dst = (uint32_t*)g_B;
    for (int e = tid; e < 128 * 56; e += 256) {
        int row = e / 56, u = e - row * 56;
        dst[(size_t)(v0 + row) * 56 + u] = sg[row * 60 + u];
    }
}

// -------- kernel 3: bf16 tensor GEMM + digitize + attn-weighted d-reduction --------
// grid (118, 16): blockIdx.y = b*2 + mc; 256 threads = 8 warps 2(M) x 4(N); warp tile 32x64.
// 2 CTAs / SM; 3-stage A pipeline.
__device__ __forceinline__ void load_a_chunk(int rowbase, int dc, uint32_t dbase, int tid) {
    const char* base = (const char*)g_A + ((size_t)(rowbase + dc * TILE_M)) * (K1 * 2);
#pragma unroll 1
    for (int i = tid; i < TILE_M * 14; i += 256) {
        int row = i / 14, u = i - row * 14;
        cpa16(dbase + row * PITCH + u * 16, base + (size_t)row * (K1 * 2) + u * 16);
    }
}

__global__ void __launch_bounds__(256, 2)
k_main(const float* __restrict__ attn) {
    extern __shared__ unsigned char sm[];
    const uint32_t sBs = smem_u32(sm);
    const uint32_t sAs = sBs + BBUF;
    float* vred = (float*)(sm + BBUF + NSTAGE * ABUF);

    const int tid  = threadIdx.x;
    const int lane = tid & 31, wid = tid >> 5;
    const int wm   = wid >> 2, wn = wid & 3;      // 2 x 4 warps
    const int by   = blockIdx.y;
    const int b    = by >> 1;
    const int mc   = by & 1;
    const int rowbase = b * ND + mc * 512;
    const int v0   = blockIdx.x * TILE_N;

    const float binw_r = __ldg(&g_binw[lane & 15]);
    const int lm_row  = lane & 15;
    const int lm_koff = (lane >> 4) << 3;

    // digitize: y = sat((t'-0.5)/15), m = rn(y*15 + 2^23), bits[4:0] = dig
    const float S2 = INV_STEP / 15.0f;
    const float C2 = (0.5f * INV_STEP + 0.5f) / 15.0f;
    const float MAGIC = 8388608.0f;   // 2^23

    // ---- prologue: B + A0 as group0; A1 as group1 ----
    {
        const char* bsrc = (const char*)g_B + (size_t)v0 * (K1 * 2);
#pragma unroll 1
        for (int i = tid; i < TILE_N * 14; i += 256) {
            int row = i / 14, u = i - row * 14;
            cpa16(sBs + row * PITCH + u * 16, bsrc + (size_t)row * (K1 * 2) + u * 16);
        }
        load_a_chunk(rowbase, 0, sAs, tid);
        cpa_commit();
        load_a_chunk(rowbase, 1, sAs + ABUF, tid);
        cpa_commit();
    }

    float vcol[16];
#pragma unroll
    for (int j = 0; j < 16; j++) vcol[j] = 0.f;

    const float* attn_b = attn + rowbase;

#pragma unroll 1
    for (int dc = 0; dc < NDC; ++dc) {
        asm volatile("cp.async.wait_group 1;");   // A[dc] (and B) complete
        __syncthreads();
        if (dc + 2 < NDC) {
            int st = (dc + 2) % NSTAGE;
            load_a_chunk(rowbase, dc + 2, sAs + (uint32_t)st * ABUF, tid);
            cpa_commit();
        }
        const uint32_t sA = sAs + (uint32_t)(dc % NSTAGE) * ABUF;

        // prefetch the 4 attn values used in this dc's epilogue
        const int arow = dc * TILE_M + wm * 32 + (lane >> 2);
        float av[2][2];
#pragma unroll
        for (int mi = 0; mi < 2; mi++)
#pragma unroll
            for (int gg = 0; gg < 2; gg++)
                av[mi][gg] = __ldg(&attn_b[arow + mi * 16 + gg * 8]);

        float acc[2][8][4];
#pragma unroll
        for (int mi = 0; mi < 2; mi++)
#pragma unroll
            for (int nj = 0; nj < 8; nj++)
#pragma unroll
                for (int q = 0; q < 4; q++) acc[mi][nj][q] = 0.f;

        // ---- 7 x k16 MMA steps ----
#pragma unroll
        for (int ks = 0; ks < K1 / 16; ks++) {
            const int kl = ks * 16;
            uint32_t a[2][4];
#pragma unroll
            for (int mi = 0; mi < 2; mi++) {
                uint32_t addr = sA + (wm * 32 + mi * 16 + lm_row) * PITCH
                              + (kl + lm_koff) * 2;
                ldm4(a[mi][0], a[mi][1], a[mi][2], a[mi][3], addr);
            }
            uint32_t bf[8][2];
#pragma unroll
            for (int nb = 0; nb < 4; nb++) {
                uint32_t addr = sBs + (wn * 64 + nb * 16 + lm_row) * PITCH
                              + (kl + lm_koff) * 2;
                uint32_t r0, r1, r2, r3;
                ldm4(r0, r1, r2, r3, addr);
                bf[nb * 2][0] = r0;     bf[nb * 2][1] = r2;
                bf[nb * 2 + 1][0] = r1; bf[nb * 2 + 1][1] = r3;
            }
#pragma unroll
            for (int mi = 0; mi < 2; mi++)
#pragma unroll
                for (int nj = 0; nj < 8; nj++)
                    mma16816(acc[mi][nj], a[mi], bf[nj]);
        }

        // ---- epilogue: 4 ops/element: sat-fma, magic-fma, shfl(raw), fma ----
#pragma unroll
        for (int mi = 0; mi < 2; mi++) {
#pragma unroll
            for (int gg = 0; gg < 2; gg++) {
                const float a_v = av[mi][gg];
#pragma unroll
                for (int nj = 0; nj < 8; nj++) {
#pragma unroll
                    for (int cc = 0; cc < 2; cc++) {
                        float s = acc[mi][nj][gg * 2 + cc];
                        float y = fma_sat(s, S2, C2);
                        float m = fmaf(y, 15.0f, MAGIC);
                        float w = shfl_idx_raw(binw_r, __float_as_uint(m));
                        vcol[nj * 2 + cc] = fmaf(a_v, w, vcol[nj * 2 + cc]);
                    }
                }
            }
        }
    }

    // ---- reduce vcol over lanes sharing the same columns ----
#pragma unroll
    for (int j = 0; j < 16; j++) {
        vcol[j] += __shfl_down_sync(0xffffffffu, vcol[j], 16);
        vcol[j] += __shfl_down_sync(0xffffffffu, vcol[j], 8);
        vcol[j] += __shfl_down_sync(0xffffffffu, vcol[j], 4);
    }
    if (lane < 4) {
#pragma unroll
        for (int j = 0; j < 16; j++) {
            int nj = j >> 1, cc = j & 1;
            vred[wid * 64 + nj * 8 + lane * 2 + cc] = vcol[j];
        }
    }
    __syncthreads();
    {
        int wn2 = tid >> 6, cl = tid & 63;
        float s = vred[wn2 * 64 + cl] + vred[(4 + wn2) * 64 + cl];
        g_weighted[(size_t)(mc * 8 + b) * NVP + v0 + tid] = s;
    }
}

// -------- kernel 4a: phi L1 + partial dots over NV chunks --------
#define CHV 7552   // NVP/4
__global__ void __launch_bounds__(256)
k_fin1(const float* __restrict__ phi) {
    const int rb  = blockIdx.x;          // 0..127 (4 concept rows each)
    const int sp  = blockIdx.y;          // 0..3   (NV chunk)
    const int n0  = rb * 4;
    const int tid = threadIdx.x;

    const int vbeg = sp * CHV;
    const int vend = (vbeg + CHV < NV) ? vbeg + CHV : NV;

    float acc[4][8];
    float l1[4];
#pragma unroll
    for (int r = 0; r < 4; r++) {
        l1[r] = 0.f;
#pragma unroll
        for (int bb = 0; bb < 8; bb++) acc[r][bb] = 0.f;
    }

    for (int base = vbeg + tid * 4; base < vend; base += 1024) {
        float4 w[8];
#pragma unroll
        for (int bb = 0; bb < 8; bb++) {
            float4 w0 = *(const float4*)&g_weighted[(size_t)bb * NVP + base];
            float4 w1 = *(const float4*)&g_weighted[(size_t)(8 + bb) * NVP + base];
            w[bb].x = w0.x + w1.x; w[bb].y = w0.y + w1.y;
            w[bb].z = w0.z + w1.z; w[bb].w = w0.w + w1.w;
        }
#pragma unroll
        for (int r = 0; r < 4; r++) {
            float4 p = *(const float4*)&phi[(size_t)(n0 + r) * NV + base];
            l1[r] += fabsf(p.x) + fabsf(p.y) + fabsf(p.z) + fabsf(p.w);
#pragma unroll
            for (int bb = 0; bb < 8; bb++)
                acc[r][bb] += p.x * w[bb].x + p.y * w[bb].y + p.z * w[bb].z + p.w * w[bb].w;
        }
    }

    const unsigned mask = 0xffffffffu;
#pragma unroll
    for (int r = 0; r < 4; r++) {
#pragma unroll
        for (int bb = 0; bb < 8; bb++)
#pragma unroll
            for (int o = 16; o > 0; o >>= 1)
                acc[r][bb] += __shfl_down_sync(mask, acc[r][bb], o);
#pragma unroll
        for (int o = 16; o > 0; o >>= 1)
            l1[r] += __shfl_down_sync(mask, l1[r], o);
    }

    __shared__ float red[8][36];
    const int wid = tid >> 5, lane = tid & 31;
    if (lane == 0) {
#pragma unroll
        for (int r = 0; r < 4; r++) {
#pragma unroll
            for (int bb = 0; bb < 8; bb++) red[wid][r * 9 + bb] = acc[r][bb];
            red[wid][r * 9 + 8] = l1[r];
        }
    }
    __syncthreads();
    if (tid < 36) {
        float s = 0.f;
#pragma unroll
        for (int w8 = 0; w8 < 8; w8++) s += red[w8][tid];
        g_part[(sp * 128 + rb) * 36 + tid] = s;
    }
}

// -------- kernel 4b: combine partials + normalize + write output --------
__global__ void __launch_bounds__(64)
k_fin2(float* __restrict__ out) {
    const int rb  = blockIdx.x;
    const int tid = threadIdx.x;
    __shared__ float tot[36];
    if (tid < 36) {
        float s = 0.f;
#pragma unroll
        for (int sp = 0; sp < 4; sp++) s += g_part[(sp * 128 + rb) * 36 + tid];
        tot[tid] = s;
    }
    __syncthreads();
    if (tid < 32) {
        int r  = tid >> 3;
        int bb = tid & 7;
        float l = tot[r * 9 + 8];
        out[bb * NC + (rb * 4 + r)] = tot[r * 9 + bb] / fmaxf(l, 1e-12f);
    }
}

// -------- launcher --------
extern "C" void kernel_launch(void* const* d_in, const int* in_sizes, int n_in,
                              void* d_out, int out_size) {
    const int*   doc_index = (const int*)d_in[0];
    const float* attn      = (const float*)d_in[1];
    const float* emb       = (const float*)d_in[2];
    const float* vvt       = (const float*)d_in[3];
    const float* phi       = (const float*)d_in[4];
    const float* diff      = (const float*)d_in[5];
    const float* start     = (const float*)d_in[6];
    float* out = (float*)d_out;

    k_binw<<<1, 32>>>(diff, start);

    k_prepA<<<(NB * ND * K1 + 511) / 512, 512>>>(doc_index, emb);
    k_prepB<<<NVP / 128, 256>>>(vvt);

    cudaFuncSetAttribute(k_main, cudaFuncAttributeMaxDynamicSharedMemorySize, SMEM_MAIN);
    dim3 grid(N_VT, NB * 2);
    k_main<<<grid, 256, SMEM_MAIN>>>(attn);

    dim3 g1(128, 4);
    k_fin1<<<g1, 256>>>(phi);
    k_fin2<<<128, 64>>>(out);
}

// round 8
// speedup vs baseline: 7.6398x; 1.0171x over previous
#include <cuda_runtime.h>
#include <cuda_bf16.h>
#include <cstdint>

#define NB   8
#define ND   1024
#define DD   100
#define NV   30000
#define NC   512

#define K1   112              // 100 + 12 zero pad (7 x k16)
#define NVP  30208            // 118 * 256
#define TILE_N 256
#define TILE_M 64
#define N_VT (NVP / TILE_N)   // 118
#define NDC  8                // 8 chunks of 64 rows = 512 rows per CTA (half of ND)

#define PITCH 240             // 15 x 16B, odd units -> conflict-free ldmatrix
#define ABUF  (TILE_M * PITCH)               // 15360
#define BBUF  (TILE_N * PITCH)               // 61440
#define NSTAGE 3
#define VRED_OFF  (BBUF + NSTAGE * ABUF)             // 107520
#define MBAR_OFF  (VRED_OFF + 8 * 64 * 4)            // 109568 (ready[3], free[3])
#define SMEM_MAIN (MBAR_OFF + 64)                    // 109632

#define INV_STEP (14.0f / 1.49f)

// -------- device scratch --------
__device__ __nv_bfloat16 g_A[(size_t)NB * ND * K1];     // [row][k] row-major, 224B rows
__device__ __nv_bfloat16 g_B[(size_t)NVP * K1];         // [v][k]
__device__ float g_weighted[16 * NVP];                  // row = mc*8 + b
__device__ float g_binw[16];
__device__ float g_part[4 * 128 * 36];

// -------- helpers --------
__device__ __forceinline__ uint32_t smem_u32(const void* p) {
    return (uint32_t)__cvta_generic_to_shared(p);
}
__device__ __forceinline__ void cpa16(uint32_t dst, const void* src) {
    asm volatile("cp.async.cg.shared.global [%0], [%1], 16;" :: "r"(dst), "l"(src));
}
// NOINC variant: arrival counts against the barrier's init count when this
// thread's prior cp.asyncs complete. (Default variant increments the expected
// count -> R7 deadlock.)
__device__ __forceinline__ void cpa_mbar_arrive_noinc(uint32_t mbar) {
    asm volatile("cp.async.mbarrier.arrive.noinc.shared.b64 [%0];" :: "r"(mbar) : "memory");
}
__device__ __forceinline__ void mbar_init(uint32_t mbar, uint32_t cnt) {
    asm volatile("mbarrier.init.shared.b64 [%0], %1;" :: "r"(mbar), "r"(cnt) : "memory");
}
__device__ __forceinline__ void mbar_arrive(uint32_t mbar) {
    asm volatile("mbarrier.arrive.shared.b64 _, [%0];" :: "r"(mbar) : "memory");
}
__device__ __forceinline__ void mbar_wait(uint32_t mbar, uint32_t parity) {
    asm volatile(
        "{\n\t.reg .pred P1;\n\t"
        "WAIT_%=:\n\t"
        "mbarrier.try_wait.parity.acquire.cta.shared::cta.b64 P1, [%0], %1, 0x989680;\n\t"
        "@P1 bra.uni DONE_%=;\n\t"
        "bra.uni WAIT_%=;\n\t"
        "DONE_%=:\n\t}"
        :: "r"(mbar), "r"(parity) : "memory");
}

__device__ __forceinline__ void ldm4(uint32_t& r0, uint32_t& r1, uint32_t& r2, uint32_t& r3,
                                     uint32_t addr) {
    asm volatile("ldmatrix.sync.aligned.m8n8.x4.shared.b16 {%0,%1,%2,%3}, [%4];"
                 : "=r"(r0), "=r"(r1), "=r"(r2), "=r"(r3) : "r"(addr));
}
__device__ __forceinline__ void mma16816(float* c, const uint32_t* a, const uint32_t* b) {
    asm volatile(
        "mma.sync.aligned.m16n8k16.row.col.f32.bf16.bf16.f32 "
        "{%0,%1,%2,%3}, {%4,%5,%6,%7}, {%8,%9}, {%0,%1,%2,%3};"
        : "+f"(c[0]), "+f"(c[1]), "+f"(c[2]), "+f"(c[3])
        : "r"(a[0]), "r"(a[1]), "r"(a[2]), "r"(a[3]), "r"(b[0]), "r"(b[1]));
}
__device__ __forceinline__ float fma_sat(float a, float b, float c) {
    float d;
    asm("fma.rn.sat.f32 %0, %1, %2, %3;" : "=f"(d) : "f"(a), "f"(b), "f"(c));
    return d;
}
// shfl.idx taking raw bits as lane index (b[4:0] used; magic guarantees low bits = dig)
__device__ __forceinline__ float shfl_idx_raw(float v, uint32_t idx) {
    float r;
    asm volatile("shfl.sync.idx.b32 %0, %1, %2, 0x1f, 0xffffffff;"
                 : "=f"(r) : "f"(v), "r"(idx));
    return r;
}

// -------- kernel 0: bin weights --------
__global__ void k_binw(const float* __restrict__ diff, const float* __restrict__ start) {
    if (threadIdx.x == 0) {
        float acc = start[0];
        for (int j = 0; j < 16; j++) {
            float d = diff[j];
            acc += d > 0.f ? d : 0.f;
            g_binw[j] = acc;
        }
    }
}

// -------- kernel 1: gather + bf16 cast of A rows --------
__global__ void k_prepA(const int* __restrict__ doc_index, const float* __restrict__ emb) {
    int e = blockIdx.x * blockDim.x + threadIdx.x;
    if (e >= NB * ND * K1) return;
    int r = e / K1;
    int k = e - r * K1;
    float val = (k < DD) ? emb[(size_t)doc_index[r] * DD + k] : 0.f;
    g_A[e] = __float2bfloat16(val);
}

// -------- kernel 2: transpose + bf16 cast of B --------
__global__ void k_prepB(const float* __restrict__ Vv_T) {
    __shared__ __nv_bfloat16 stage[128 * 120];
    const int tid = threadIdx.x;
    const int v0 = blockIdx.x * 128;

    for (int idx = tid; idx < DD * 128; idx += 256) {
        int k = idx >> 7, c = idx & 127;
        int v = v0 + c;
        float val = (v < NV) ? Vv_T[(size_t)k * NV + v] : 0.f;
        stage[c * 120 + k] = __float2bfloat16(val);
    }
    for (int idx = tid; idx < 128 * 12; idx += 256) {
        int c = idx / 12, u = idx - c * 12;
        stage[c * 120 + DD + u] = __float2bfloat16(0.f);
    }
    __syncthreads();
    const uint32_t* sg = (const uint32_t*)stage;
    uint32_t* dst = (uint32_t*)g_B;
    for (int e = tid; e < 128 * 56; e += 256) {
        int row = e / 56, u = e - row * 56;
        dst[(size_t)(v0 + row) * 56 + u] = sg[row * 60 + u];
    }
}

// -------- kernel 3: bf16 tensor GEMM + digitize + attn-weighted d-reduction --------
// grid (118, 16): blockIdx.y = b*2 + mc; 256 threads = 8 warps 2(M) x 4(N); warp tile 32x64.
// 2 CTAs / SM; 3-stage A ring with mbarrier producer/consumer (no per-dc __syncthreads).
__device__ __forceinline__ void load_a_chunk(int rowbase, int dc, uint32_t dbase, int tid) {
    const char* base = (const char*)g_A + ((size_t)(rowbase + dc * TILE_M)) * (K1 * 2);
#pragma unroll 1
    for (int i = tid; i < TILE_M * 14; i += 256) {
        int row = i / 14, u = i - row * 14;
        cpa16(dbase + row * PITCH + u * 16, base + (size_t)row * (K1 * 2) + u * 16);
    }
}

__global__ void __launch_bounds__(256, 2)
k_main(const float* __restrict__ attn) {
    extern __shared__ unsigned char sm[];
    const uint32_t sBs = smem_u32(sm);
    const uint32_t sAs = sBs + BBUF;
    float* vred = (float*)(sm + VRED_OFF);
    const uint32_t mb_ready = sBs + MBAR_OFF;        // 3 x 8B
    const uint32_t mb_free  = sBs + MBAR_OFF + 24;   // 3 x 8B

    const int tid  = threadIdx.x;
    const int lane = tid & 31, wid = tid >> 5;
    const int wm   = wid >> 2, wn = wid & 3;      // 2 x 4 warps
    const int by   = blockIdx.y;
    const int b    = by >> 1;
    const int mc   = by & 1;
    const int rowbase = b * ND + mc * 512;
    const int v0   = blockIdx.x * TILE_N;

    const float binw_r = __ldg(&g_binw[lane & 15]);
    const int lm_row  = lane & 15;
    const int lm_koff = (lane >> 4) << 3;

    // digitize: y = sat((t'-0.5)/15), m = rn(y*15 + 2^23), bits[4:0] = dig
    const float S2 = INV_STEP / 15.0f;
    const float C2 = (0.5f * INV_STEP + 0.5f) / 15.0f;
    const float MAGIC = 8388608.0f;   // 2^23

    // ---- init mbarriers, then make visible ----
    if (tid == 0) {
#pragma unroll
        for (int s = 0; s < 3; s++) {
            mbar_init(mb_ready + s * 8, 256);
            mbar_init(mb_free  + s * 8, 8);
        }
    }
    __syncthreads();

    // ---- prologue: B + A0 -> ready[0]; A1 -> ready[1] ----
    {
        const char* bsrc = (const char*)g_B + (size_t)v0 * (K1 * 2);
#pragma unroll 1
        for (int i = tid; i < TILE_N * 14; i += 256) {
            int row = i / 14, u = i - row * 14;
            cpa16(sBs + row * PITCH + u * 16, bsrc + (size_t)row * (K1 * 2) + u * 16);
        }
        load_a_chunk(rowbase, 0, sAs, tid);
        cpa_mbar_arrive_noinc(mb_ready + 0 * 8);     // B + A0 tracked
        load_a_chunk(rowbase, 1, sAs + ABUF, tid);
        cpa_mbar_arrive_noinc(mb_ready + 1 * 8);
    }

    float vcol[16];
#pragma unroll
    for (int j = 0; j < 16; j++) vcol[j] = 0.f;

    const float* attn_b = attn + rowbase;

#pragma unroll 1
    for (int dc = 0; dc < NDC; ++dc) {
        const int slot = dc % NSTAGE;

        // 1. wait A[dc] (and B, folded into ready[0]) ready
        mbar_wait(mb_ready + slot * 8, (uint32_t)((dc / 3) & 1));

        // 2. prefetch A[dc+2] into slot (dc+2)%3 (wait for its readers first)
        if (dc + 2 < NDC) {
            const int ps = (dc + 2) % NSTAGE;
            if (dc >= 1)
                mbar_wait(mb_free + ps * 8, (uint32_t)(((dc - 1) / 3) & 1));
            load_a_chunk(rowbase, dc + 2, sAs + (uint32_t)ps * ABUF, tid);
            cpa_mbar_arrive_noinc(mb_ready + ps * 8);
        }

        const uint32_t sA = sAs + (uint32_t)slot * ABUF;

        // prefetch the 4 attn values used in this dc's epilogue
        const int arow = dc * TILE_M + wm * 32 + (lane >> 2);
        float av[2][2];
#pragma unroll
        for (int mi = 0; mi < 2; mi++)
#pragma unroll
            for (int gg = 0; gg < 2; gg++)
                av[mi][gg] = __ldg(&attn_b[arow + mi * 16 + gg * 8]);

        float acc[2][8][4];
#pragma unroll
        for (int mi = 0; mi < 2; mi++)
#pragma unroll
            for (int nj = 0; nj < 8; nj++)
#pragma unroll
                for (int q = 0; q < 4; q++) acc[mi][nj][q] = 0.f;

        // ---- 3. 7 x k16 MMA steps ----
#pragma unroll
        for (int ks = 0; ks < K1 / 16; ks++) {
            const int kl = ks * 16;
            uint32_t a[2][4];
#pragma unroll
            for (int mi = 0; mi < 2; mi++) {
                uint32_t addr = sA + (wm * 32 + mi * 16 + lm_row) * PITCH
                              + (kl + lm_koff) * 2;
                ldm4(a[mi][0], a[mi][1], a[mi][2], a[mi][3], addr);
            }
            uint32_t bf[8][2];
#pragma unroll
            for (int nb = 0; nb < 4; nb++) {
                uint32_t addr = sBs + (wn * 64 + nb * 16 + lm_row) * PITCH
                              + (kl + lm_koff) * 2;
                uint32_t r0, r1, r2, r3;
                ldm4(r0, r1, r2, r3, addr);
                bf[nb * 2][0] = r0;     bf[nb * 2][1] = r2;
                bf[nb * 2 + 1][0] = r1; bf[nb * 2 + 1][1] = r3;
            }
#pragma unroll
            for (int mi = 0; mi < 2; mi++)
#pragma unroll
                for (int nj = 0; nj < 8; nj++)
                    mma16816(acc[mi][nj], a[mi], bf[nj]);
        }

        // 4. this warp is done reading A stage 'slot' (MMA issue waits on LDSM
        //    scoreboard; volatile asm order keeps this after the MMAs)
        if (lane == 0) mbar_arrive(mb_free + slot * 8);

        // ---- 5. epilogue (registers only): sat-fma, magic-fma, shfl(raw), fma ----
#pragma unroll
        for (int mi = 0; mi < 2; mi++) {
#pragma unroll
            for (int gg = 0; gg < 2; gg++) {
                const float a_v = av[mi][gg];
#pragma unroll
                for (int nj = 0; nj < 8; nj++) {
#pragma unroll
                    for (int cc = 0; cc < 2; cc++) {
                        float s = acc[mi][nj][gg * 2 + cc];
                        float y = fma_sat(s, S2, C2);
                        float m = fmaf(y, 15.0f, MAGIC);
                        float w = shfl_idx_raw(binw_r, __float_as_uint(m));
                        vcol[nj * 2 + cc] = fmaf(a_v, w, vcol[nj * 2 + cc]);
                    }
                }
            }
        }
    }

    // ---- reduce vcol over lanes sharing the same columns ----
#pragma unroll
    for (int j = 0; j < 16; j++) {
        vcol[j] += __shfl_down_sync(0xffffffffu, vcol[j], 16);
        vcol[j] += __shfl_down_sync(0xffffffffu, vcol[j], 8);
        vcol[j] += __shfl_down_sync(0xffffffffu, vcol[j], 4);
    }
    if (lane < 4) {
#pragma unroll
        for (int j = 0; j < 16; j++) {
            int nj = j >> 1, cc = j & 1;
            vred[wid * 64 + nj * 8 + lane * 2 + cc] = vcol[j];
        }
    }
    __syncthreads();
    {
        int wn2 = tid >> 6, cl = tid & 63;
        float s = vred[wn2 * 64 + cl] + vred[(4 + wn2) * 64 + cl];
        g_weighted[(size_t)(mc * 8 + b) * NVP + v0 + tid] = s;
    }
}

// -------- kernel 4a: phi L1 + partial dots over NV chunks --------
#define CHV 7552   // NVP/4
__global__ void __launch_bounds__(256)
k_fin1(const float* __restrict__ phi) {
    const int rb  = blockIdx.x;          // 0..127 (4 concept rows each)
    const int sp  = blockIdx.y;          // 0..3   (NV chunk)
    const int n0  = rb * 4;
    const int tid = threadIdx.x;

    const int vbeg = sp * CHV;
    const int vend = (vbeg + CHV < NV) ? vbeg + CHV : NV;

    float acc[4][8];
    float l1[4];
#pragma unroll
    for (int r = 0; r < 4; r++) {
        l1[r] = 0.f;
#pragma unroll
        for (int bb = 0; bb < 8; bb++) acc[r][bb] = 0.f;
    }

    for (int base = vbeg + tid * 4; base < vend; base += 1024) {
        float4 w[8];
#pragma unroll
        for (int bb = 0; bb < 8; bb++) {
            float4 w0 = *(const float4*)&g_weighted[(size_t)bb * NVP + base];
            float4 w1 = *(const float4*)&g_weighted[(size_t)(8 + bb) * NVP + base];
            w[bb].x = w0.x + w1.x; w[bb].y = w0.y + w1.y;
            w[bb].z = w0.z + w1.z; w[bb].w = w0.w + w1.w;
        }
#pragma unroll
        for (int r = 0; r < 4; r++) {
            float4 p = *(const float4*)&phi[(size_t)(n0 + r) * NV + base];
            l1[r] += fabsf(p.x) + fabsf(p.y) + fabsf(p.z) + fabsf(p.w);
#pragma unroll
            for (int bb = 0; bb < 8; bb++)
                acc[r][bb] += p.x * w[bb].x + p.y * w[bb].y + p.z * w[bb].z + p.w * w[bb].w;
        }
    }

    const unsigned mask = 0xffffffffu;
#pragma unroll
    for (int r = 0; r < 4; r++) {
#pragma unroll
        for (int bb = 0; bb < 8; bb++)
#pragma unroll
            for (int o = 16; o > 0; o >>= 1)
                acc[r][bb] += __shfl_down_sync(mask, acc[r][bb], o);
#pragma unroll
        for (int o = 16; o > 0; o >>= 1)
            l1[r] += __shfl_down_sync(mask, l1[r], o);
    }

    __shared__ float red[8][36];
    const int wid = tid >> 5, lane = tid & 31;
    if (lane == 0) {
#pragma unroll
        for (int r = 0; r < 4; r++) {
#pragma unroll
            for (int bb = 0; bb < 8; bb++) red[wid][r * 9 + bb] = acc[r][bb];
            red[wid][r * 9 + 8] = l1[r];
        }
    }
    __syncthreads();
    if (tid < 36) {
        float s = 0.f;
#pragma unroll
        for (int w8 = 0; w8 < 8; w8++) s += red[w8][tid];
        g_part[(sp * 128 + rb) * 36 + tid] = s;
    }
}

// -------- kernel 4b: combine partials + normalize + write output --------
__global__ void __launch_bounds__(64)
k_fin2(float* __restrict__ out) {
    const int rb  = blockIdx.x;
    const int tid = threadIdx.x;
    __shared__ float tot[36];
    if (tid < 36) {
        float s = 0.f;
#pragma unroll
        for (int sp = 0; sp < 4; sp++) s += g_part[(sp * 128 + rb) * 36 + tid];
        tot[tid] = s;
    }
    __syncthreads();
    if (tid < 32) {
        int r  = tid >> 3;
        int bb = tid & 7;
        float l = tot[r * 9 + 8];
        out[bb * NC + (rb * 4 + r)] = tot[r * 9 + bb] / fmaxf(l, 1e-12f);
    }
}

// -------- launcher --------
extern "C" void kernel_launch(void* const* d_in, const int* in_sizes, int n_in,
                              void* d_out, int out_size) {
    const int*   doc_index = (const int*)d_in[0];
    const float* attn      = (const float*)d_in[1];
    const float* emb       = (const float*)d_in[2];
    const float* vvt       = (const float*)d_in[3];
    const float* phi       = (const float*)d_in[4];
    const float* diff      = (const float*)d_in[5];
    const float* start     = (const float*)d_in[6];
    float* out = (float*)d_out;

    k_binw<<<1, 32>>>(diff, start);

    k_prepA<<<(NB * ND * K1 + 511) / 512, 512>>>(doc_index, emb);
    k_prepB<<<NVP / 128, 256>>>(vvt);

    cudaFuncSetAttribute(k_main, cudaFuncAttributeMaxDynamicSharedMemorySize, SMEM_MAIN);
    dim3 grid(N_VT, NB * 2);
    k_main<<<grid, 256, SMEM_MAIN>>>(attn);

    dim3 g1(128, 4);
    k_fin1<<<g1, 256>>>(phi);
    k_fin2<<<128, 64>>>(out);
}